// round 12
// baseline (speedup 1.0000x reference)
#include <cuda_runtime.h>
#include <cuda_fp16.h>
#include <cstdint>

#define Bb   4
#define Nn   2048
#define Hh   8
#define HG   2            // heads per CTA in gat_mma
#define IN_D 128
#define Oo   32
#define LOG2E 1.44269504f

#define BI   64           // rows per CTA (MMA M)
#define KC   16           // j per chunk (one m16n8k16 K-step)
#define NCH  (Nn/KC)      // 128 chunks

// ---------------- scratch (device globals) ----------------------------------
__device__ __half g_WhT[(size_t)Bb*Hh*Oo*Nn];   // [b][h][o][n], fp16
__device__ float  g_asrc[(size_t)Bb*Hh*Nn];
__device__ float  g_adst[(size_t)Bb*Hh*Nn];
__device__ float  g_maxd[Bb*Hh];

__device__ __forceinline__ float ex2f_fast(float x) {
    float r; asm("ex2.approx.ftz.f32 %0, %1;" : "=f"(r) : "f"(x)); return r;
}
// pack two floats to fp16x2: lo half = lo_f, hi half = hi_f
__device__ __forceinline__ uint32_t f2h2(float hi_f, float lo_f) {
    uint32_t r;
    asm("cvt.rn.f16x2.f32 %0, %1, %2;" : "=r"(r) : "f"(hi_f), "f"(lo_f));
    return r;
}
__device__ __forceinline__ __half2 u2h2(uint32_t u) {
    __half2 h; *(uint32_t*)&h = u; return h;
}
__device__ __forceinline__ uint32_t h2u2(__half2 h) {
    return *(uint32_t*)&h;
}
__device__ __forceinline__ void cp_async16(uint32_t dst, const void* src) {
    asm volatile("cp.async.cg.shared.global [%0], [%1], 16;"
                 :: "r"(dst), "l"(src));
}

// ============================================================================
// Kernel 1: WhT[b][h][o][n] fp16 + alpha_src/alpha_dst (fp32)
// grid (Nn/32, Hh, Bb) = 2048 CTAs, 256 threads, one head per CTA.
// ============================================================================
__global__ __launch_bounds__(256, 4) void wh_kernel(
    const float* __restrict__ x, const float* __restrict__ W,
    const float* __restrict__ a_src, const float* __restrict__ a_dst)
{
    __shared__ __align__(16) float x_sm[32][IN_D];      // 16 KB
    __shared__ __align__(16) float w_sm[IN_D * Oo];     // 16 KB (reused: 32x33 transpose)

    const int b   = blockIdx.z;
    const int h   = blockIdx.y;
    const int n0  = blockIdx.x * 32;
    const int tid = threadIdx.x;
    const int lane = tid & 31;       // = o
    const int wq   = tid >> 5;       // warp -> 4 rows

    {   // x tile
        const float4* xg = (const float4*)(x + ((size_t)b*Nn + n0)*IN_D);
        float4* xs = (float4*)&x_sm[0][0];
        #pragma unroll
        for (int k = 0; k < 4; ++k) xs[tid + k*256] = xg[tid + k*256];
    }
    {   // W[h]
        const float4* wg = (const float4*)(W + (size_t)h*IN_D*Oo);
        float4* ws = (float4*)w_sm;
        #pragma unroll
        for (int k = 0; k < 4; ++k) ws[tid + k*256] = wg[tid + k*256];
    }
    __syncthreads();

    float acc[4] = {0.f, 0.f, 0.f, 0.f};
    #pragma unroll 8
    for (int f4 = 0; f4 < IN_D/4; ++f4) {
        float4 xv[4];
        #pragma unroll
        for (int r = 0; r < 4; ++r)
            xv[r] = ((const float4*)&x_sm[wq*4 + r][0])[f4];
        #pragma unroll
        for (int u = 0; u < 4; ++u) {
            float wv = w_sm[(f4*4 + u)*Oo + lane];
            acc[0] += (u==0?xv[0].x:u==1?xv[0].y:u==2?xv[0].z:xv[0].w) * wv;
            acc[1] += (u==0?xv[1].x:u==1?xv[1].y:u==2?xv[1].z:xv[1].w) * wv;
            acc[2] += (u==0?xv[2].x:u==1?xv[2].y:u==2?xv[2].z:xv[2].w) * wv;
            acc[3] += (u==0?xv[3].x:u==1?xv[3].y:u==2?xv[3].z:xv[3].w) * wv;
        }
    }

    const float asv = a_src[h*Oo + lane];
    const float adv = a_dst[h*Oo + lane];
    #pragma unroll
    for (int r = 0; r < 4; ++r) {
        int n = n0 + wq*4 + r;
        float ps = acc[r] * asv;
        float pd = acc[r] * adv;
        #pragma unroll
        for (int s = 16; s > 0; s >>= 1) {
            ps += __shfl_xor_sync(~0u, ps, s);
            pd += __shfl_xor_sync(~0u, pd, s);
        }
        if (lane == 0) {
            g_asrc[((size_t)b*Hh + h)*Nn + n] = ps;
            g_adst[((size_t)b*Hh + h)*Nn + n] = pd;
        }
    }

    // transpose via w_sm overlay (everyone done reading w_sm)
    __syncthreads();
    #pragma unroll
    for (int r = 0; r < 4; ++r)
        w_sm[(wq*4 + r)*33 + lane] = acc[r];
    __syncthreads();

    // WhT half store: [o][n], thread writes 4 n-halves (8B), coalesced
    {
        int o  = tid >> 3;
        int ng = tid & 7;
        float v0 = w_sm[(ng*4 + 0)*33 + o];
        float v1 = w_sm[(ng*4 + 1)*33 + o];
        float v2 = w_sm[(ng*4 + 2)*33 + o];
        float v3 = w_sm[(ng*4 + 3)*33 + o];
        uint2 pk;
        pk.x = f2h2(v1, v0);
        pk.y = f2h2(v3, v2);
        *(uint2*)(g_WhT + (((size_t)b*Hh + h)*Oo + o)*Nn + n0 + ng*4) = pk;
    }
}

// ============================================================================
// Kernel 2: per-(b,h) max of alpha_dst
// ============================================================================
__global__ __launch_bounds__(256) void maxd_kernel()
{
    const int bh  = blockIdx.x;
    const int tid = threadIdx.x;
    float m = -1e30f;
    for (int n = tid; n < Nn; n += 256)
        m = fmaxf(m, g_adst[(size_t)bh*Nn + n]);
    __shared__ float red[256];
    red[tid] = m;
    __syncthreads();
    for (int s = 128; s > 0; s >>= 1) {
        if (tid < s) red[tid] = fmaxf(red[tid], red[tid + s]);
        __syncthreads();
    }
    if (tid == 0) g_maxd[bh] = red[0];
}

// ============================================================================
// Kernel 3: fused masked-softmax + AV via mma.sync.m16n8k16.f16 (fp32 accum)
// grid (32, 4, 4) = 512 CTAs; 256 threads; 2 heads/CTA; 3 CTAs/SM (6 w/SMSP).
// Warp w: head hL = w>>2 (0..1), m-tile mt = w&3 (16 rows each).
// Z via ones-column MMA (R10 scheme). Single __syncthreads per chunk.
// SMEM (dynamic, 18688 B):
//   p_sm  half [2][2][64][24]   bytes 0..12287
//   wh_sm half [2][2][32][24]   bytes 12288..18431   ([o][k] rows)
//   ej_sm      [2][2][4][16B]   bytes 18432..18687   {e1_01,e1_23,e2_01,e2_23}
// ============================================================================
__global__ __launch_bounds__(256, 3) void gat_mma(const float* __restrict__ adj,
                                                  float* __restrict__ out)
{
    extern __shared__ char smraw[];
    __half* p_sm  = (__half*)smraw;                  // halves, row stride 48 B
    __half* wh_sm = (__half*)(smraw + 12288);        // halves, row stride 48 B
    char*   ej_sm = smraw + 18432;

    const int tid  = threadIdx.x;
    const int lane = tid & 31;
    const int wid  = tid >> 5;       // 0..7
    const int hL   = wid >> 2;       // local mma head 0..1
    const int mt   = wid & 3;        // m-tile (16 rows)
    const int b    = blockIdx.z;
    const int h0   = blockIdx.y * HG;
    const int i0   = blockIdx.x * BI;
    const int ith  = tid >> 2;       // p-gen row 0..63
    const int j4   = tid & 3;        // p-gen j-quad
    const int iglob = i0 + ith;
    const int g  = lane >> 2;
    const int t4 = lane & 3;
    // ej staging (tid<16): thread -> (head, j-pair)
    const int zh = tid >> 3;         // head 0..1
    const int zp = tid & 7;          // j-pair 0..7
    // wh cp.async mapping (tid<128): 1 x 16B per thread per chunk
    const int sh = tid >> 6;         // head 0..1
    const int so = (tid >> 1) & 31;  // o-row
    const int sk = tid & 1;          // 16B half-row

    const uint32_t wh_u32 = (uint32_t)__cvta_generic_to_shared(wh_sm);

    // per-(h,i) hoisted exponentials as half2 broadcasts
    __half2 E1i2[HG], E2i2[HG];
    #pragma unroll
    for (int h = 0; h < HG; ++h) {
        float s  = g_asrc[((size_t)(b*Hh + h0 + h))*Nn + iglob];
        float md = g_maxd[b*Hh + h0 + h];
        float t  = s + md;
        float m  = fmaxf(t, 0.2f*t);                 // lrelu monotone -> row max
        E1i2[h] = __float2half2_rn(ex2f_fast((s - m)*LOG2E));
        E2i2[h] = __float2half2_rn(ex2f_fast((0.2f*s - m)*LOG2E));
    }

    const float4*  arow  = (const float4*)(adj + ((size_t)b*Nn + iglob)*Nn);
    const __half*  whtg  = g_WhT + (((size_t)b*Hh + h0)*Oo)*Nn;
    const float*   adstb = g_adst + ((size_t)b*Hh + h0)*Nn;

    // ---- prologue: cp.async wh chunk 0 -> buf 0 ----
    if (tid < 128)
        cp_async16(wh_u32 + (uint32_t)(sh*1536 + so*48 + sk*16),
                   whtg + ((size_t)sh*Oo + so)*Nn + sk*8);
    asm volatile("cp.async.commit_group;" ::: "memory");

    // ej chunk 0 -> buf 0; prefetch chunk-1 dl pair
    float2 dlv = make_float2(0.f, 0.f);
    if (tid < 16) {
        float2 d0 = *(const float2*)(adstb + (size_t)zh*Nn + zp*2);
        float a0 = d0.x*LOG2E, a1 = d0.y*LOG2E;
        uint32_t e1 = f2h2(ex2f_fast(a1), ex2f_fast(a0));
        uint32_t e2 = f2h2(ex2f_fast(0.2f*a1), ex2f_fast(0.2f*a0));
        int base = zh*64 + (zp>>1)*16 + (zp&1)*4;
        *(uint32_t*)(ej_sm + base)     = e1;
        *(uint32_t*)(ej_sm + base + 8) = e2;
        dlv = *(const float2*)(adstb + (size_t)zh*Nn + KC + zp*2);
    }
    float4 adjv = arow[j4];          // chunk-0 adj

    float acc[4][4];                 // [nt][r], one m16-tile per warp
    float accz[4];
    #pragma unroll
    for (int nt = 0; nt < 4; ++nt)
        #pragma unroll
        for (int r = 0; r < 4; ++r) acc[nt][r] = 0.f;
    #pragma unroll
    for (int r = 0; r < 4; ++r) accz[r] = 0.f;
    // ones-column B fragment (constant): lanes with g==0 hold column n=0
    const uint32_t bones = (g == 0) ? 0x3C003C00u : 0u;

    __syncthreads();                 // ej[0] visible

    for (int c = 0; c < NCH; ++c) {
        const int buf = c & 1;
        const int jb  = c*KC + j4*4;

        // ======== phase A ========
        // stage ej(c+1) -> ej[buf^1]
        if (c + 1 < NCH && tid < 16) {
            float a0 = dlv.x*LOG2E, a1 = dlv.y*LOG2E;
            uint32_t e1 = f2h2(ex2f_fast(a1), ex2f_fast(a0));
            uint32_t e2 = f2h2(ex2f_fast(0.2f*a1), ex2f_fast(0.2f*a0));
            int base = (buf^1)*128 + zh*64 + (zp>>1)*16 + (zp&1)*4;
            *(uint32_t*)(ej_sm + base)     = e1;
            *(uint32_t*)(ej_sm + base + 8) = e2;
        }

        // masks as half2 pairs (shared across the 2 heads)
        float m0 = (adjv.x > 0.f || (jb + 0) == iglob) ? 1.f : 0.f;
        float m1 = (adjv.y > 0.f || (jb + 1) == iglob) ? 1.f : 0.f;
        float m2 = (adjv.z > 0.f || (jb + 2) == iglob) ? 1.f : 0.f;
        float m3 = (adjv.w > 0.f || (jb + 3) == iglob) ? 1.f : 0.f;
        __half2 msk01 = u2h2(f2h2(m1, m0));
        __half2 msk23 = u2h2(f2h2(m3, m2));

        // p-gen for 2 heads -> p[buf] (half2 SIMD)
        #pragma unroll
        for (int h = 0; h < HG; ++h) {
            uint4 e = *(const uint4*)(ej_sm + buf*128 + h*64 + j4*16);
            __half2 w01 = __hmax2(__hmul2(E1i2[h], u2h2(e.x)),
                                  __hmul2(E2i2[h], u2h2(e.z)));
            __half2 w23 = __hmax2(__hmul2(E1i2[h], u2h2(e.y)),
                                  __hmul2(E2i2[h], u2h2(e.w)));
            w01 = __hmul2(w01, msk01);
            w23 = __hmul2(w23, msk23);
            uint2 pk; pk.x = h2u2(w01); pk.y = h2u2(w23);
            *(uint2*)((char*)p_sm + buf*6144 + h*3072 + ith*48 + j4*8) = pk;
        }

        __syncthreads();             // the ONE barrier per chunk

        // ======== phase B ========
        if (c + 1 < NCH) {
            if (tid < 128)
                cp_async16(wh_u32 + (uint32_t)((buf^1)*3072 + sh*1536 + so*48 + sk*16),
                           whtg + ((size_t)sh*Oo + so)*Nn + (c+1)*KC + sk*8);
            asm volatile("cp.async.commit_group;" ::: "memory");
            asm volatile("cp.async.wait_group 1;" ::: "memory");
        } else {
            asm volatile("cp.async.wait_group 0;" ::: "memory");
        }

        // mma: warp (hL, mt) reads p[buf], wh[buf]; one m16n8k16 K-step
        {
            const __half* ph = (const __half*)((char*)p_sm + buf*6144 + hL*3072
                                               + mt*768);
            const __half* wt = (const __half*)((char*)wh_sm + buf*3072 + hL*1536);
            uint32_t bf[4][2];
            #pragma unroll
            for (int nt = 0; nt < 4; ++nt) {
                const __half* br = wt + (nt*8 + g)*24;
                bf[nt][0] = *(const uint32_t*)(br + 2*t4);
                bf[nt][1] = *(const uint32_t*)(br + 2*t4 + 8);
            }
            const __half* pa  = ph + g*24;
            const __half* pa8 = pa + 8*24;
            uint32_t a0 = *(const uint32_t*)(pa  + 2*t4);
            uint32_t a1 = *(const uint32_t*)(pa8 + 2*t4);
            uint32_t a2 = *(const uint32_t*)(pa  + 2*t4 + 8);
            uint32_t a3 = *(const uint32_t*)(pa8 + 2*t4 + 8);
            #pragma unroll
            for (int nt = 0; nt < 4; ++nt) {
                asm volatile(
                  "mma.sync.aligned.m16n8k16.row.col.f32.f16.f16.f32 "
                  "{%0,%1,%2,%3}, {%4,%5,%6,%7}, {%8,%9}, {%0,%1,%2,%3};"
                  : "+f"(acc[nt][0]), "+f"(acc[nt][1]),
                    "+f"(acc[nt][2]), "+f"(acc[nt][3])
                  : "r"(a0), "r"(a1), "r"(a2), "r"(a3),
                    "r"(bf[nt][0]), "r"(bf[nt][1]));
            }
            // Z accumulation: ones-column B (register constant)
            asm volatile(
              "mma.sync.aligned.m16n8k16.row.col.f32.f16.f16.f32 "
              "{%0,%1,%2,%3}, {%4,%5,%6,%7}, {%8,%9}, {%0,%1,%2,%3};"
              : "+f"(accz[0]), "+f"(accz[1]), "+f"(accz[2]), "+f"(accz[3])
              : "r"(a0), "r"(a1), "r"(a2), "r"(a3),
                "r"(bones), "r"(bones));
        }

        // prefetches
        if (c + 1 < NCH) adjv = arow[(c+1)*4 + j4];
        if (c + 2 < NCH && tid < 16)
            dlv = *(const float2*)(adstb + (size_t)zh*Nn + (c+2)*KC + zp*2);
    }

    // ---- epilogue: Z broadcast (t4==0 lanes hold column 0), normalize ----
    {
        float* ob = out + ((size_t)b*Nn + i0 + mt*16)*(Hh*Oo) + (h0 + hL)*Oo;
        float z0 = __shfl_sync(~0u, accz[0], lane & ~3);
        float z1 = __shfl_sync(~0u, accz[2], lane & ~3);
        float zi0 = 1.f / z0;
        float zi1 = 1.f / z1;
        #pragma unroll
        for (int nt = 0; nt < 4; ++nt) {
            int o = nt*8 + 2*t4;
            float2 v0, v1;
            v0.x = fmaxf(acc[nt][0]*zi0, 0.f);
            v0.y = fmaxf(acc[nt][1]*zi0, 0.f);
            v1.x = fmaxf(acc[nt][2]*zi1, 0.f);
            v1.y = fmaxf(acc[nt][3]*zi1, 0.f);
            *(float2*)(ob + (size_t)g*(Hh*Oo) + o)       = v0;
            *(float2*)(ob + (size_t)(g + 8)*(Hh*Oo) + o) = v1;
        }
    }
}

// ============================================================================
extern "C" void kernel_launch(void* const* d_in, const int* in_sizes, int n_in,
                              void* d_out, int out_size)
{
    (void)in_sizes; (void)n_in; (void)out_size;
    const float* x     = (const float*)d_in[0];
    const float* adj   = (const float*)d_in[1];
    const float* W     = (const float*)d_in[2];
    const float* a_src = (const float*)d_in[3];
    const float* a_dst = (const float*)d_in[4];
    float* out = (float*)d_out;

    wh_kernel<<<dim3(Nn/32, Hh, Bb), 256>>>(x, W, a_src, a_dst);
    maxd_kernel<<<Bb*Hh, 256>>>();

    static const int smem_bytes = 18688;
    cudaFuncSetAttribute(gat_mma, cudaFuncAttributeMaxDynamicSharedMemorySize,
                         smem_bytes);
    gat_mma<<<dim3(Nn/BI, Hh/HG, Bb), 256, smem_bytes>>>(adj, out);
}

// round 13
// speedup vs baseline: 1.3148x; 1.3148x over previous
#include <cuda_runtime.h>
#include <cuda_fp16.h>
#include <cstdint>

#define Bb   4
#define Nn   2048
#define Hh   8
#define HG   4            // heads per CTA in gat_mma
#define IN_D 128
#define Oo   32
#define LOG2E 1.44269504f

#define BI   32           // rows per CTA (2 x m16 tiles)
#define KC   16           // j per chunk (one m16n8k16 K-step)
#define NCH  (Nn/KC)      // 128 chunks

// ---------------- scratch (device globals) ----------------------------------
__device__ __half g_WhT[(size_t)Bb*Hh*Oo*Nn];   // [b][h][o][n], fp16
__device__ float  g_asrc[(size_t)Bb*Hh*Nn];
__device__ float  g_adst[(size_t)Bb*Hh*Nn];
__device__ float  g_maxd[Bb*Hh];

__device__ __forceinline__ float ex2f_fast(float x) {
    float r; asm("ex2.approx.ftz.f32 %0, %1;" : "=f"(r) : "f"(x)); return r;
}
// pack two floats to fp16x2: lo half = lo_f, hi half = hi_f
__device__ __forceinline__ uint32_t f2h2(float hi_f, float lo_f) {
    uint32_t r;
    asm("cvt.rn.f16x2.f32 %0, %1, %2;" : "=r"(r) : "f"(hi_f), "f"(lo_f));
    return r;
}
__device__ __forceinline__ __half2 u2h2(uint32_t u) {
    __half2 h; *(uint32_t*)&h = u; return h;
}
__device__ __forceinline__ uint32_t h2u2(__half2 h) {
    return *(uint32_t*)&h;
}
__device__ __forceinline__ void cp_async16(uint32_t dst, const void* src) {
    asm volatile("cp.async.cg.shared.global [%0], [%1], 16;"
                 :: "r"(dst), "l"(src));
}

// ============================================================================
// Kernel 1: WhT[b][h][o][n] fp16 + alpha_src/alpha_dst (fp32)
// grid (Nn/32, Hh, Bb) = 2048 CTAs, 256 threads, one head per CTA.
// ============================================================================
__global__ __launch_bounds__(256, 4) void wh_kernel(
    const float* __restrict__ x, const float* __restrict__ W,
    const float* __restrict__ a_src, const float* __restrict__ a_dst)
{
    __shared__ __align__(16) float x_sm[32][IN_D];      // 16 KB
    __shared__ __align__(16) float w_sm[IN_D * Oo];     // 16 KB (reused: 32x33 transpose)

    const int b   = blockIdx.z;
    const int h   = blockIdx.y;
    const int n0  = blockIdx.x * 32;
    const int tid = threadIdx.x;
    const int lane = tid & 31;       // = o
    const int wq   = tid >> 5;       // warp -> 4 rows

    {   // x tile
        const float4* xg = (const float4*)(x + ((size_t)b*Nn + n0)*IN_D);
        float4* xs = (float4*)&x_sm[0][0];
        #pragma unroll
        for (int k = 0; k < 4; ++k) xs[tid + k*256] = xg[tid + k*256];
    }
    {   // W[h]
        const float4* wg = (const float4*)(W + (size_t)h*IN_D*Oo);
        float4* ws = (float4*)w_sm;
        #pragma unroll
        for (int k = 0; k < 4; ++k) ws[tid + k*256] = wg[tid + k*256];
    }
    __syncthreads();

    float acc[4] = {0.f, 0.f, 0.f, 0.f};
    #pragma unroll 8
    for (int f4 = 0; f4 < IN_D/4; ++f4) {
        float4 xv[4];
        #pragma unroll
        for (int r = 0; r < 4; ++r)
            xv[r] = ((const float4*)&x_sm[wq*4 + r][0])[f4];
        #pragma unroll
        for (int u = 0; u < 4; ++u) {
            float wv = w_sm[(f4*4 + u)*Oo + lane];
            acc[0] += (u==0?xv[0].x:u==1?xv[0].y:u==2?xv[0].z:xv[0].w) * wv;
            acc[1] += (u==0?xv[1].x:u==1?xv[1].y:u==2?xv[1].z:xv[1].w) * wv;
            acc[2] += (u==0?xv[2].x:u==1?xv[2].y:u==2?xv[2].z:xv[2].w) * wv;
            acc[3] += (u==0?xv[3].x:u==1?xv[3].y:u==2?xv[3].z:xv[3].w) * wv;
        }
    }

    const float asv = a_src[h*Oo + lane];
    const float adv = a_dst[h*Oo + lane];
    #pragma unroll
    for (int r = 0; r < 4; ++r) {
        int n = n0 + wq*4 + r;
        float ps = acc[r] * asv;
        float pd = acc[r] * adv;
        #pragma unroll
        for (int s = 16; s > 0; s >>= 1) {
            ps += __shfl_xor_sync(~0u, ps, s);
            pd += __shfl_xor_sync(~0u, pd, s);
        }
        if (lane == 0) {
            g_asrc[((size_t)b*Hh + h)*Nn + n] = ps;
            g_adst[((size_t)b*Hh + h)*Nn + n] = pd;
        }
    }

    // transpose via w_sm overlay (everyone done reading w_sm)
    __syncthreads();
    #pragma unroll
    for (int r = 0; r < 4; ++r)
        w_sm[(wq*4 + r)*33 + lane] = acc[r];
    __syncthreads();

    // WhT half store: [o][n], thread writes 4 n-halves (8B), coalesced
    {
        int o  = tid >> 3;
        int ng = tid & 7;
        float v0 = w_sm[(ng*4 + 0)*33 + o];
        float v1 = w_sm[(ng*4 + 1)*33 + o];
        float v2 = w_sm[(ng*4 + 2)*33 + o];
        float v3 = w_sm[(ng*4 + 3)*33 + o];
        uint2 pk;
        pk.x = f2h2(v1, v0);
        pk.y = f2h2(v3, v2);
        *(uint2*)(g_WhT + (((size_t)b*Hh + h)*Oo + o)*Nn + n0 + ng*4) = pk;
    }
}

// ============================================================================
// Kernel 2: per-(b,h) max of alpha_dst
// ============================================================================
__global__ __launch_bounds__(256) void maxd_kernel()
{
    const int bh  = blockIdx.x;
    const int tid = threadIdx.x;
    float m = -1e30f;
    for (int n = tid; n < Nn; n += 256)
        m = fmaxf(m, g_adst[(size_t)bh*Nn + n]);
    __shared__ float red[256];
    red[tid] = m;
    __syncthreads();
    for (int s = 128; s > 0; s >>= 1) {
        if (tid < s) red[tid] = fmaxf(red[tid], red[tid + s]);
        __syncthreads();
    }
    if (tid == 0) g_maxd[bh] = red[0];
}

// ============================================================================
// Kernel 3: fused masked-softmax + AV via mma.sync.m16n8k16.f16 (fp32 accum)
// grid (64, 2, 4) = 512 CTAs; 128 threads; 4 heads/CTA; BI=32 rows/CTA.
// ALL 512 CTAs co-resident: 4 CTAs/SM x 132 SMs = 528 slots (no wave-2 tail),
// barriers sync only 4 warps, 4 independent CTAs interleave per SM.
// Warp w = head hL; each warp owns 2 m16 tiles (rows 0-15, 16-31).
// Z via ones-column MMA. Single __syncthreads per chunk (R10 schedule).
// SMEM (dynamic, 25088 B):
//   p_sm  half [2][4][32][24]   bytes 0..12287      (row stride 48 B)
//   wh_sm half [2][4][32][24]   bytes 12288..24575  ([o][k] rows, stride 48 B)
//   ej_sm      [2][4][4][16B]   bytes 24576..25087  {e1_01,e1_23,e2_01,e2_23}
// ============================================================================
__global__ __launch_bounds__(128, 4) void gat_mma(const float* __restrict__ adj,
                                                  float* __restrict__ out)
{
    extern __shared__ char smraw[];
    __half* p_sm  = (__half*)smraw;                  // halves, row stride 48 B
    __half* wh_sm = (__half*)(smraw + 12288);        // halves, row stride 48 B
    char*   ej_sm = smraw + 24576;

    const int tid  = threadIdx.x;
    const int lane = tid & 31;
    const int hL   = tid >> 5;       // warp = local mma head 0..3
    const int b    = blockIdx.z;
    const int h0   = blockIdx.y * HG;
    const int i0   = blockIdx.x * BI;
    const int ith  = tid >> 2;       // p-gen row 0..31
    const int j4   = tid & 3;        // p-gen j-quad
    const int iglob = i0 + ith;
    const int g  = lane >> 2;
    const int t4 = lane & 3;
    // ej staging (tid<32): thread -> (head, j-pair)
    const int zh = tid >> 3;         // head 0..3
    const int zp = tid & 7;          // j-pair 0..7
    // wh cp.async mapping: 2 x 16B per thread per chunk (q = tid + r*128)
    const uint32_t wh_u32 = (uint32_t)__cvta_generic_to_shared(wh_sm);

    // per-(h,i) hoisted exponentials as half2 broadcasts
    __half2 E1i2[HG], E2i2[HG];
    #pragma unroll
    for (int h = 0; h < HG; ++h) {
        float s  = g_asrc[((size_t)(b*Hh + h0 + h))*Nn + iglob];
        float md = g_maxd[b*Hh + h0 + h];
        float t  = s + md;
        float m  = fmaxf(t, 0.2f*t);                 // lrelu monotone -> row max
        E1i2[h] = __float2half2_rn(ex2f_fast((s - m)*LOG2E));
        E2i2[h] = __float2half2_rn(ex2f_fast((0.2f*s - m)*LOG2E));
    }

    const float4*  arow  = (const float4*)(adj + ((size_t)b*Nn + iglob)*Nn);
    const __half*  whtg  = g_WhT + (((size_t)b*Hh + h0)*Oo)*Nn;
    const float*   adstb = g_adst + ((size_t)b*Hh + h0)*Nn;

    // ---- prologue: cp.async wh chunk 0 -> buf 0 ----
    #pragma unroll
    for (int r = 0; r < 2; ++r) {
        int q  = tid + r*128;            // 0..255
        int sh = q >> 6, so = (q >> 1) & 31, sk = q & 1;
        cp_async16(wh_u32 + (uint32_t)(sh*1536 + so*48 + sk*16),
                   whtg + ((size_t)sh*Oo + so)*Nn + sk*8);
    }
    asm volatile("cp.async.commit_group;" ::: "memory");

    // ej chunk 0 -> buf 0; prefetch chunk-1 dl pair
    float2 dlv = make_float2(0.f, 0.f);
    if (tid < 32) {
        float2 d0 = *(const float2*)(adstb + (size_t)zh*Nn + zp*2);
        float a0 = d0.x*LOG2E, a1 = d0.y*LOG2E;
        uint32_t e1 = f2h2(ex2f_fast(a1), ex2f_fast(a0));
        uint32_t e2 = f2h2(ex2f_fast(0.2f*a1), ex2f_fast(0.2f*a0));
        int base = zh*64 + (zp>>1)*16 + (zp&1)*4;
        *(uint32_t*)(ej_sm + base)     = e1;
        *(uint32_t*)(ej_sm + base + 8) = e2;
        dlv = *(const float2*)(adstb + (size_t)zh*Nn + KC + zp*2);
    }
    float4 adjv = arow[j4];          // chunk-0 adj

    float acc[2][4][4];              // [mt][nt][r], two m16 tiles per warp
    float accz[2][4];
    #pragma unroll
    for (int mt = 0; mt < 2; ++mt) {
        #pragma unroll
        for (int nt = 0; nt < 4; ++nt)
            #pragma unroll
            for (int r = 0; r < 4; ++r) acc[mt][nt][r] = 0.f;
        #pragma unroll
        for (int r = 0; r < 4; ++r) accz[mt][r] = 0.f;
    }
    // ones-column B fragment (constant): lanes with g==0 hold column n=0
    const uint32_t bones = (g == 0) ? 0x3C003C00u : 0u;

    __syncthreads();                 // ej[0] visible

    for (int c = 0; c < NCH; ++c) {
        const int buf = c & 1;
        const int jb  = c*KC + j4*4;

        // ======== phase A ========
        // stage ej(c+1) -> ej[buf^1]
        if (c + 1 < NCH && tid < 32) {
            float a0 = dlv.x*LOG2E, a1 = dlv.y*LOG2E;
            uint32_t e1 = f2h2(ex2f_fast(a1), ex2f_fast(a0));
            uint32_t e2 = f2h2(ex2f_fast(0.2f*a1), ex2f_fast(0.2f*a0));
            int base = (buf^1)*256 + zh*64 + (zp>>1)*16 + (zp&1)*4;
            *(uint32_t*)(ej_sm + base)     = e1;
            *(uint32_t*)(ej_sm + base + 8) = e2;
        }

        // masks as half2 pairs (shared across the 4 heads)
        float m0 = (adjv.x > 0.f || (jb + 0) == iglob) ? 1.f : 0.f;
        float m1 = (adjv.y > 0.f || (jb + 1) == iglob) ? 1.f : 0.f;
        float m2 = (adjv.z > 0.f || (jb + 2) == iglob) ? 1.f : 0.f;
        float m3 = (adjv.w > 0.f || (jb + 3) == iglob) ? 1.f : 0.f;
        __half2 msk01 = u2h2(f2h2(m1, m0));
        __half2 msk23 = u2h2(f2h2(m3, m2));

        // p-gen for 4 heads -> p[buf] (half2 SIMD)
        #pragma unroll
        for (int h = 0; h < HG; ++h) {
            uint4 e = *(const uint4*)(ej_sm + buf*256 + h*64 + j4*16);
            __half2 w01 = __hmax2(__hmul2(E1i2[h], u2h2(e.x)),
                                  __hmul2(E2i2[h], u2h2(e.z)));
            __half2 w23 = __hmax2(__hmul2(E1i2[h], u2h2(e.y)),
                                  __hmul2(E2i2[h], u2h2(e.w)));
            w01 = __hmul2(w01, msk01);
            w23 = __hmul2(w23, msk23);
            uint2 pk; pk.x = h2u2(w01); pk.y = h2u2(w23);
            *(uint2*)((char*)p_sm + buf*6144 + h*1536 + ith*48 + j4*8) = pk;
        }

        __syncthreads();             // the ONE barrier per chunk

        // ======== phase B ========
        if (c + 1 < NCH) {
            #pragma unroll
            for (int r = 0; r < 2; ++r) {
                int q  = tid + r*128;
                int sh = q >> 6, so = (q >> 1) & 31, sk = q & 1;
                cp_async16(wh_u32 + (uint32_t)((buf^1)*6144 + sh*1536 + so*48 + sk*16),
                           whtg + ((size_t)sh*Oo + so)*Nn + (c+1)*KC + sk*8);
            }
            asm volatile("cp.async.commit_group;" ::: "memory");
            asm volatile("cp.async.wait_group 1;" ::: "memory");
        } else {
            asm volatile("cp.async.wait_group 0;" ::: "memory");
        }

        // mma: warp hL reads p[buf] (2 m-tiles), wh[buf]; one k16 K-step each
        {
            const __half* ph = (const __half*)((char*)p_sm + buf*6144 + hL*1536);
            const __half* wt = (const __half*)((char*)wh_sm + buf*6144 + hL*1536);
            uint32_t bf[4][2];
            #pragma unroll
            for (int nt = 0; nt < 4; ++nt) {
                const __half* br = wt + (nt*8 + g)*24;
                bf[nt][0] = *(const uint32_t*)(br + 2*t4);
                bf[nt][1] = *(const uint32_t*)(br + 2*t4 + 8);
            }
            #pragma unroll
            for (int mt = 0; mt < 2; ++mt) {
                const __half* pa  = ph + (mt*16 + g)*24;
                const __half* pa8 = pa + 8*24;
                uint32_t a0 = *(const uint32_t*)(pa  + 2*t4);
                uint32_t a1 = *(const uint32_t*)(pa8 + 2*t4);
                uint32_t a2 = *(const uint32_t*)(pa  + 2*t4 + 8);
                uint32_t a3 = *(const uint32_t*)(pa8 + 2*t4 + 8);
                #pragma unroll
                for (int nt = 0; nt < 4; ++nt) {
                    asm volatile(
                      "mma.sync.aligned.m16n8k16.row.col.f32.f16.f16.f32 "
                      "{%0,%1,%2,%3}, {%4,%5,%6,%7}, {%8,%9}, {%0,%1,%2,%3};"
                      : "+f"(acc[mt][nt][0]), "+f"(acc[mt][nt][1]),
                        "+f"(acc[mt][nt][2]), "+f"(acc[mt][nt][3])
                      : "r"(a0), "r"(a1), "r"(a2), "r"(a3),
                        "r"(bf[nt][0]), "r"(bf[nt][1]));
                }
                // Z accumulation: ones-column B (register constant)
                asm volatile(
                  "mma.sync.aligned.m16n8k16.row.col.f32.f16.f16.f32 "
                  "{%0,%1,%2,%3}, {%4,%5,%6,%7}, {%8,%9}, {%0,%1,%2,%3};"
                  : "+f"(accz[mt][0]), "+f"(accz[mt][1]),
                    "+f"(accz[mt][2]), "+f"(accz[mt][3])
                  : "r"(a0), "r"(a1), "r"(a2), "r"(a3),
                    "r"(bones), "r"(bones));
            }
        }

        // prefetches
        if (c + 1 < NCH) adjv = arow[(c+1)*4 + j4];
        if (c + 2 < NCH && tid < 32)
            dlv = *(const float2*)(adstb + (size_t)zh*Nn + (c+2)*KC + zp*2);
    }

    // ---- epilogue: Z broadcast (t4==0 lanes hold column 0), normalize ----
    {
        #pragma unroll
        for (int mt = 0; mt < 2; ++mt) {
            float* ob = out + ((size_t)b*Nn + i0 + mt*16)*(Hh*Oo) + (h0 + hL)*Oo;
            float z0 = __shfl_sync(~0u, accz[mt][0], lane & ~3);
            float z1 = __shfl_sync(~0u, accz[mt][2], lane & ~3);
            float zi0 = 1.f / z0;
            float zi1 = 1.f / z1;
            #pragma unroll
            for (int nt = 0; nt < 4; ++nt) {
                int o = nt*8 + 2*t4;
                float2 v0, v1;
                v0.x = fmaxf(acc[mt][nt][0]*zi0, 0.f);
                v0.y = fmaxf(acc[mt][nt][1]*zi0, 0.f);
                v1.x = fmaxf(acc[mt][nt][2]*zi1, 0.f);
                v1.y = fmaxf(acc[mt][nt][3]*zi1, 0.f);
                *(float2*)(ob + (size_t)g*(Hh*Oo) + o)       = v0;
                *(float2*)(ob + (size_t)(g + 8)*(Hh*Oo) + o) = v1;
            }
        }
    }
}

// ============================================================================
extern "C" void kernel_launch(void* const* d_in, const int* in_sizes, int n_in,
                              void* d_out, int out_size)
{
    (void)in_sizes; (void)n_in; (void)out_size;
    const float* x     = (const float*)d_in[0];
    const float* adj   = (const float*)d_in[1];
    const float* W     = (const float*)d_in[2];
    const float* a_src = (const float*)d_in[3];
    const float* a_dst = (const float*)d_in[4];
    float* out = (float*)d_out;

    wh_kernel<<<dim3(Nn/32, Hh, Bb), 256>>>(x, W, a_src, a_dst);
    maxd_kernel<<<Bb*Hh, 256>>>();

    static const int smem_bytes = 25088;
    cudaFuncSetAttribute(gat_mma, cudaFuncAttributeMaxDynamicSharedMemorySize,
                         smem_bytes);
    gat_mma<<<dim3(Nn/BI, Hh/HG, Bb), 128, smem_bytes>>>(adj, out);
}

// round 14
// speedup vs baseline: 1.4981x; 1.1394x over previous
#include <cuda_runtime.h>
#include <cuda_fp16.h>
#include <cstdint>

#define Bb   4
#define Nn   2048
#define Hh   8
#define HG   4            // heads per CTA in gat_mma
#define IN_D 128
#define Oo   32
#define LOG2E 1.44269504f

#define BI   64           // rows per CTA (MMA M)
#define KC   16           // j per sub-chunk (one m16n8k16 K-step)
#define ITN  64           // iterations; 2 sub-chunks (32 j) per iteration

// ---------------- scratch (device globals) ----------------------------------
__device__ __half g_WhT[(size_t)Bb*Hh*Oo*Nn];   // [b][h][o][n], fp16
__device__ float  g_asrc[(size_t)Bb*Hh*Nn];
__device__ float  g_adst[(size_t)Bb*Hh*Nn];
__device__ float  g_maxd[Bb*Hh];

__device__ __forceinline__ float ex2f_fast(float x) {
    float r; asm("ex2.approx.ftz.f32 %0, %1;" : "=f"(r) : "f"(x)); return r;
}
// pack two floats to fp16x2: lo half = lo_f, hi half = hi_f
__device__ __forceinline__ uint32_t f2h2(float hi_f, float lo_f) {
    uint32_t r;
    asm("cvt.rn.f16x2.f32 %0, %1, %2;" : "=r"(r) : "f"(hi_f), "f"(lo_f));
    return r;
}
__device__ __forceinline__ __half2 u2h2(uint32_t u) {
    __half2 h; *(uint32_t*)&h = u; return h;
}
__device__ __forceinline__ uint32_t h2u2(__half2 h) {
    return *(uint32_t*)&h;
}
__device__ __forceinline__ void cp_async16(uint32_t dst, const void* src) {
    asm volatile("cp.async.cg.shared.global [%0], [%1], 16;"
                 :: "r"(dst), "l"(src));
}

// ============================================================================
// Kernel 1: WhT[b][h][o][n] fp16 + alpha_src/alpha_dst (fp32)
// ============================================================================
__global__ __launch_bounds__(256, 4) void wh_kernel(
    const float* __restrict__ x, const float* __restrict__ W,
    const float* __restrict__ a_src, const float* __restrict__ a_dst)
{
    __shared__ __align__(16) float x_sm[32][IN_D];      // 16 KB
    __shared__ __align__(16) float w_sm[IN_D * Oo];     // 16 KB (reused: 32x33 transpose)

    const int b   = blockIdx.z;
    const int h   = blockIdx.y;
    const int n0  = blockIdx.x * 32;
    const int tid = threadIdx.x;
    const int lane = tid & 31;       // = o
    const int wq   = tid >> 5;       // warp -> 4 rows

    {   // x tile
        const float4* xg = (const float4*)(x + ((size_t)b*Nn + n0)*IN_D);
        float4* xs = (float4*)&x_sm[0][0];
        #pragma unroll
        for (int k = 0; k < 4; ++k) xs[tid + k*256] = xg[tid + k*256];
    }
    {   // W[h]
        const float4* wg = (const float4*)(W + (size_t)h*IN_D*Oo);
        float4* ws = (float4*)w_sm;
        #pragma unroll
        for (int k = 0; k < 4; ++k) ws[tid + k*256] = wg[tid + k*256];
    }
    __syncthreads();

    float acc[4] = {0.f, 0.f, 0.f, 0.f};
    #pragma unroll 8
    for (int f4 = 0; f4 < IN_D/4; ++f4) {
        float4 xv[4];
        #pragma unroll
        for (int r = 0; r < 4; ++r)
            xv[r] = ((const float4*)&x_sm[wq*4 + r][0])[f4];
        #pragma unroll
        for (int u = 0; u < 4; ++u) {
            float wv = w_sm[(f4*4 + u)*Oo + lane];
            acc[0] += (u==0?xv[0].x:u==1?xv[0].y:u==2?xv[0].z:xv[0].w) * wv;
            acc[1] += (u==0?xv[1].x:u==1?xv[1].y:u==2?xv[1].z:xv[1].w) * wv;
            acc[2] += (u==0?xv[2].x:u==1?xv[2].y:u==2?xv[2].z:xv[2].w) * wv;
            acc[3] += (u==0?xv[3].x:u==1?xv[3].y:u==2?xv[3].z:xv[3].w) * wv;
        }
    }

    const float asv = a_src[h*Oo + lane];
    const float adv = a_dst[h*Oo + lane];
    #pragma unroll
    for (int r = 0; r < 4; ++r) {
        int n = n0 + wq*4 + r;
        float ps = acc[r] * asv;
        float pd = acc[r] * adv;
        #pragma unroll
        for (int s = 16; s > 0; s >>= 1) {
            ps += __shfl_xor_sync(~0u, ps, s);
            pd += __shfl_xor_sync(~0u, pd, s);
        }
        if (lane == 0) {
            g_asrc[((size_t)b*Hh + h)*Nn + n] = ps;
            g_adst[((size_t)b*Hh + h)*Nn + n] = pd;
        }
    }

    // transpose via w_sm overlay (everyone done reading w_sm)
    __syncthreads();
    #pragma unroll
    for (int r = 0; r < 4; ++r)
        w_sm[(wq*4 + r)*33 + lane] = acc[r];
    __syncthreads();

    // WhT half store: [o][n], thread writes 4 n-halves (8B), coalesced
    {
        int o  = tid >> 3;
        int ng = tid & 7;
        float v0 = w_sm[(ng*4 + 0)*33 + o];
        float v1 = w_sm[(ng*4 + 1)*33 + o];
        float v2 = w_sm[(ng*4 + 2)*33 + o];
        float v3 = w_sm[(ng*4 + 3)*33 + o];
        uint2 pk;
        pk.x = f2h2(v1, v0);
        pk.y = f2h2(v3, v2);
        *(uint2*)(g_WhT + (((size_t)b*Hh + h)*Oo + o)*Nn + n0 + ng*4) = pk;
    }
}

// ============================================================================
// Kernel 2: per-(b,h) max of alpha_dst
// ============================================================================
__global__ __launch_bounds__(256) void maxd_kernel()
{
    const int bh  = blockIdx.x;
    const int tid = threadIdx.x;
    float m = -1e30f;
    for (int n = tid; n < Nn; n += 256)
        m = fmaxf(m, g_adst[(size_t)bh*Nn + n]);
    __shared__ float red[256];
    red[tid] = m;
    __syncthreads();
    for (int s = 128; s > 0; s >>= 1) {
        if (tid < s) red[tid] = fmaxf(red[tid], red[tid + s]);
        __syncthreads();
    }
    if (tid == 0) g_maxd[bh] = red[0];
}

// ============================================================================
// Kernel 3: fused masked-softmax + AV via mma.sync.m16n8k16.f16 (fp32 accum)
// grid (32, 2, 4) = 256 CTAs; 256 threads; 4 heads/CTA; 2 CTAs/SM.
// R10 skeleton, TWO changes:
//  - masks taken DIRECTLY from adj (values are exactly 0.0/1.0); self-loop
//    applied as a precomputed OR-patch in the single diagonal iteration.
//  - 2 sub-chunks (32 j) per iteration: 64 barriers instead of 128, halved
//    loop/cp.async/commit/wait overhead. 4 sub-buffers, same safety proof.
// SMEM (dynamic, 74752 B):
//   p_sm  half [4][4][64][24]   bytes 0..49151      (sub-buffer stride 12288)
//   wh_sm half [4][4][32][24]   bytes 49152..73727  (sub-buffer stride 6144)
//   ej_sm      [4][4][4][16B]   bytes 73728..74751
// ============================================================================
__global__ __launch_bounds__(256, 2) void gat_mma(const float* __restrict__ adj,
                                                  float* __restrict__ out)
{
    extern __shared__ char smraw[];
    __half* p_sm  = (__half*)smraw;                  // halves, row stride 48 B
    __half* wh_sm = (__half*)(smraw + 49152);        // halves, row stride 48 B
    char*   ej_sm = smraw + 73728;

    const int tid  = threadIdx.x;
    const int lane = tid & 31;
    const int wid  = tid >> 5;       // 0..7
    const int hL   = wid >> 1;       // local mma head 0..3
    const int mh   = wid & 1;        // row half
    const int b    = blockIdx.z;
    const int h0   = blockIdx.y * HG;
    const int i0   = blockIdx.x * BI;
    const int ith  = tid >> 2;       // p-gen row 0..63
    const int j4   = tid & 3;        // p-gen j-quad within sub-chunk
    const int iglob = i0 + ith;
    const int g  = lane >> 2;
    const int t4 = lane & 3;
    // ej staging (tid<64): thread -> (sub, head, j-pair)
    const int zs = tid >> 5;         // sub-chunk 0..1
    const int zh = (tid >> 3) & 3;   // head 0..3
    const int zp = tid & 7;          // j-pair 0..7
    // wh cp.async mapping: per sub-chunk, tid covers 4h x 32o x 2sk
    const int sh = tid >> 6;         // head 0..3
    const int so = (tid >> 1) & 31;  // o-row
    const int sk = tid & 1;          // 16B half-row

    const uint32_t wh_u32 = (uint32_t)__cvta_generic_to_shared(wh_sm);

    // per-(h,i) hoisted exponentials as half2 broadcasts
    __half2 E1i2[HG], E2i2[HG];
    #pragma unroll
    for (int h = 0; h < HG; ++h) {
        float s  = g_asrc[((size_t)(b*Hh + h0 + h))*Nn + iglob];
        float md = g_maxd[b*Hh + h0 + h];
        float t  = s + md;
        float m  = fmaxf(t, 0.2f*t);                 // lrelu monotone -> row max
        E1i2[h] = __float2half2_rn(ex2f_fast((s - m)*LOG2E));
        E2i2[h] = __float2half2_rn(ex2f_fast((0.2f*s - m)*LOG2E));
    }

    // self-loop patch: fires at iteration itd, sub-chunk sd, only if this
    // thread's j-quad contains the diagonal column of its row
    const int itd = iglob >> 5;
    const int sd  = (iglob >> 4) & 1;
    const bool dhit = (((iglob >> 2) & 3) == j4);
    const int du = iglob & 3;
    const uint32_t fix01 = dhit ? (du==0 ? 0x3C00u : du==1 ? 0x3C000000u : 0u) : 0u;
    const uint32_t fix23 = dhit ? (du==2 ? 0x3C00u : du==3 ? 0x3C000000u : 0u) : 0u;

    const float4*  arow  = (const float4*)(adj + ((size_t)b*Nn + iglob)*Nn);
    const __half*  whtg  = g_WhT + (((size_t)b*Hh + h0)*Oo)*Nn;
    const float*   adstb = g_adst + ((size_t)b*Hh + h0)*Nn;

    // ---- prologue: cp.async wh iteration 0 (both sub-chunks) -> bufs 0,1 ----
    #pragma unroll
    for (int s = 0; s < 2; ++s)
        cp_async16(wh_u32 + (uint32_t)(s*6144 + sh*1536 + so*48 + sk*16),
                   whtg + ((size_t)sh*Oo + so)*Nn + s*KC + sk*8);
    asm volatile("cp.async.commit_group;" ::: "memory");

    // ej iteration 0 -> bufs 0,1; prefetch iteration-1 dl pair
    float2 dlv = make_float2(0.f, 0.f);
    if (tid < 64) {
        float2 d0 = *(const float2*)(adstb + (size_t)zh*Nn + zs*KC + zp*2);
        float a0 = d0.x*LOG2E, a1 = d0.y*LOG2E;
        uint32_t e1 = f2h2(ex2f_fast(a1), ex2f_fast(a0));
        uint32_t e2 = f2h2(ex2f_fast(0.2f*a1), ex2f_fast(0.2f*a0));
        int base = zs*256 + zh*64 + (zp>>1)*16 + (zp&1)*4;
        *(uint32_t*)(ej_sm + base)     = e1;
        *(uint32_t*)(ej_sm + base + 8) = e2;
        dlv = *(const float2*)(adstb + (size_t)zh*Nn + 32 + zs*KC + zp*2);
    }
    float4 adjv0 = arow[j4];          // iteration-0 adj, sub 0
    float4 adjv1 = arow[4 + j4];      // iteration-0 adj, sub 1

    float acc[2][4][4];
    float accz[2][4];
    #pragma unroll
    for (int m = 0; m < 2; ++m) {
        #pragma unroll
        for (int nt = 0; nt < 4; ++nt)
            #pragma unroll
            for (int r = 0; r < 4; ++r) acc[m][nt][r] = 0.f;
        #pragma unroll
        for (int r = 0; r < 4; ++r) accz[m][r] = 0.f;
    }
    // ones-column B fragment (constant): lanes with g==0 hold column n=0
    const uint32_t bones = (g == 0) ? 0x3C003C00u : 0u;

    __syncthreads();                 // ej[0,1] visible

    for (int it = 0; it < ITN; ++it) {
        const int pb = (it & 1) * 2; // sub-buffer pair base (0 or 2)

        // ======== phase A ========
        // stage ej(it+1) -> bufs pb^2, pb^2+1
        if (it + 1 < ITN && tid < 64) {
            float a0 = dlv.x*LOG2E, a1 = dlv.y*LOG2E;
            uint32_t e1 = f2h2(ex2f_fast(a1), ex2f_fast(a0));
            uint32_t e2 = f2h2(ex2f_fast(0.2f*a1), ex2f_fast(0.2f*a0));
            int base = ((pb^2) + zs)*256 + zh*64 + (zp>>1)*16 + (zp&1)*4;
            *(uint32_t*)(ej_sm + base)     = e1;
            *(uint32_t*)(ej_sm + base + 8) = e2;
        }

        // p-gen for both sub-chunks x 4 heads
        #pragma unroll
        for (int s = 0; s < 2; ++s) {
            const float4 av = s ? adjv1 : adjv0;
            // masks DIRECTLY from adj (exact 0.0/1.0), diagonal OR-patch
            uint32_t m01u = f2h2(av.y, av.x);
            uint32_t m23u = f2h2(av.w, av.z);
            if (it == itd && s == sd) { m01u |= fix01; m23u |= fix23; }
            const __half2 msk01 = u2h2(m01u);
            const __half2 msk23 = u2h2(m23u);
            const int sb = pb + s;
            #pragma unroll
            for (int h = 0; h < HG; ++h) {
                uint4 e = *(const uint4*)(ej_sm + sb*256 + h*64 + j4*16);
                __half2 w01 = __hmax2(__hmul2(E1i2[h], u2h2(e.x)),
                                      __hmul2(E2i2[h], u2h2(e.z)));
                __half2 w23 = __hmax2(__hmul2(E1i2[h], u2h2(e.y)),
                                      __hmul2(E2i2[h], u2h2(e.w)));
                w01 = __hmul2(w01, msk01);
                w23 = __hmul2(w23, msk23);
                uint2 pk; pk.x = h2u2(w01); pk.y = h2u2(w23);
                *(uint2*)((char*)p_sm + sb*12288 + h*3072 + ith*48 + j4*8) = pk;
            }
        }

        __syncthreads();             // the ONE barrier per iteration

        // ======== phase B ========
        if (it + 1 < ITN) {
            #pragma unroll
            for (int s = 0; s < 2; ++s)
                cp_async16(wh_u32 + (uint32_t)(((pb^2)+s)*6144 + sh*1536 + so*48 + sk*16),
                           whtg + ((size_t)sh*Oo + so)*Nn + (it+1)*32 + s*KC + sk*8);
            asm volatile("cp.async.commit_group;" ::: "memory");
            asm volatile("cp.async.wait_group 1;" ::: "memory");
        } else {
            asm volatile("cp.async.wait_group 0;" ::: "memory");
        }

        // mma over both sub-chunks: warp (hL, mh)
        #pragma unroll
        for (int s = 0; s < 2; ++s) {
            const int sb = pb + s;
            const __half* ph = (const __half*)((char*)p_sm + sb*12288 + hL*3072
                                               + mh*32*48);
            const __half* wt = (const __half*)((char*)wh_sm + sb*6144 + hL*1536);
            uint32_t bf[4][2];
            #pragma unroll
            for (int nt = 0; nt < 4; ++nt) {
                const __half* br = wt + (nt*8 + g)*24;
                bf[nt][0] = *(const uint32_t*)(br + 2*t4);
                bf[nt][1] = *(const uint32_t*)(br + 2*t4 + 8);
            }
            #pragma unroll
            for (int m = 0; m < 2; ++m) {
                const __half* pa  = ph + (m*16 + g)*24;
                const __half* pa8 = pa + 8*24;
                uint32_t a0 = *(const uint32_t*)(pa  + 2*t4);
                uint32_t a1 = *(const uint32_t*)(pa8 + 2*t4);
                uint32_t a2 = *(const uint32_t*)(pa  + 2*t4 + 8);
                uint32_t a3 = *(const uint32_t*)(pa8 + 2*t4 + 8);
                #pragma unroll
                for (int nt = 0; nt < 4; ++nt) {
                    asm volatile(
                      "mma.sync.aligned.m16n8k16.row.col.f32.f16.f16.f32 "
                      "{%0,%1,%2,%3}, {%4,%5,%6,%7}, {%8,%9}, {%0,%1,%2,%3};"
                      : "+f"(acc[m][nt][0]), "+f"(acc[m][nt][1]),
                        "+f"(acc[m][nt][2]), "+f"(acc[m][nt][3])
                      : "r"(a0), "r"(a1), "r"(a2), "r"(a3),
                        "r"(bf[nt][0]), "r"(bf[nt][1]));
                }
                // Z accumulation: ones-column B (register constant)
                asm volatile(
                  "mma.sync.aligned.m16n8k16.row.col.f32.f16.f16.f32 "
                  "{%0,%1,%2,%3}, {%4,%5,%6,%7}, {%8,%9}, {%0,%1,%2,%3};"
                  : "+f"(accz[m][0]), "+f"(accz[m][1]),
                    "+f"(accz[m][2]), "+f"(accz[m][3])
                  : "r"(a0), "r"(a1), "r"(a2), "r"(a3),
                    "r"(bones), "r"(bones));
            }
        }

        // prefetches for it+1 / it+2
        if (it + 1 < ITN) {
            adjv0 = arow[(it+1)*8 + j4];
            adjv1 = arow[(it+1)*8 + 4 + j4];
        }
        if (it + 2 < ITN && tid < 64)
            dlv = *(const float2*)(adstb + (size_t)zh*Nn + (it+2)*32 + zs*KC + zp*2);
    }

    // ---- epilogue: Z broadcast (t4==0 lanes hold column 0), normalize ----
    {
        float* ob = out + ((size_t)b*Nn + i0 + mh*32)*(Hh*Oo) + (h0 + hL)*Oo;
        #pragma unroll
        for (int m = 0; m < 2; ++m) {
            int r0 = m*16 + g;
            float z0 = __shfl_sync(~0u, accz[m][0], lane & ~3);
            float z1 = __shfl_sync(~0u, accz[m][2], lane & ~3);
            float zi0 = 1.f / z0;
            float zi1 = 1.f / z1;
            #pragma unroll
            for (int nt = 0; nt < 4; ++nt) {
                int o = nt*8 + 2*t4;
                float2 v0, v1;
                v0.x = fmaxf(acc[m][nt][0]*zi0, 0.f);
                v0.y = fmaxf(acc[m][nt][1]*zi0, 0.f);
                v1.x = fmaxf(acc[m][nt][2]*zi1, 0.f);
                v1.y = fmaxf(acc[m][nt][3]*zi1, 0.f);
                *(float2*)(ob + (size_t)r0*(Hh*Oo) + o)       = v0;
                *(float2*)(ob + (size_t)(r0 + 8)*(Hh*Oo) + o) = v1;
            }
        }
    }
}

// ============================================================================
extern "C" void kernel_launch(void* const* d_in, const int* in_sizes, int n_in,
                              void* d_out, int out_size)
{
    (void)in_sizes; (void)n_in; (void)out_size;
    const float* x     = (const float*)d_in[0];
    const float* adj   = (const float*)d_in[1];
    const float* W     = (const float*)d_in[2];
    const float* a_src = (const float*)d_in[3];
    const float* a_dst = (const float*)d_in[4];
    float* out = (float*)d_out;

    wh_kernel<<<dim3(Nn/32, Hh, Bb), 256>>>(x, W, a_src, a_dst);
    maxd_kernel<<<Bb*Hh, 256>>>();

    static const int smem_bytes = 74752;
    cudaFuncSetAttribute(gat_mma, cudaFuncAttributeMaxDynamicSharedMemorySize,
                         smem_bytes);
    gat_mma<<<dim3(Nn/BI, Hh/HG, Bb), 256, smem_bytes>>>(adj, out);
}

// round 16
// speedup vs baseline: 1.5472x; 1.0327x over previous
#include <cuda_runtime.h>
#include <cuda_fp16.h>
#include <cstdint>

#define Bb   4
#define Nn   2048
#define Hh   8
#define HG   4            // heads per CTA in gat_mma
#define IN_D 128
#define Oo   32
#define LOG2E 1.44269504f

#define BI   64           // rows per CTA (MMA M)
#define KC   16           // j per sub-chunk (one m16n8k16 K-step)
#define ITN  64           // iterations; 2 sub-chunks (32 j) per iteration

// ---------------- scratch (device globals) ----------------------------------
__device__ __half g_WhT[(size_t)Bb*Hh*Oo*Nn];   // [b][h][o][n], fp16
__device__ float  g_asrc[(size_t)Bb*Hh*Nn];
__device__ float  g_adst[(size_t)Bb*Hh*Nn];
__device__ float  g_maxd[Bb*Hh];

__device__ __forceinline__ float ex2f_fast(float x) {
    float r; asm("ex2.approx.ftz.f32 %0, %1;" : "=f"(r) : "f"(x)); return r;
}
// pack two floats to fp16x2: lo half = lo_f, hi half = hi_f
__device__ __forceinline__ uint32_t f2h2(float hi_f, float lo_f) {
    uint32_t r;
    asm("cvt.rn.f16x2.f32 %0, %1, %2;" : "=r"(r) : "f"(hi_f), "f"(lo_f));
    return r;
}
__device__ __forceinline__ __half2 u2h2(uint32_t u) {
    __half2 h; *(uint32_t*)&h = u; return h;
}
__device__ __forceinline__ uint32_t h2u2(__half2 h) {
    return *(uint32_t*)&h;
}
__device__ __forceinline__ void cp_async16(uint32_t dst, const void* src) {
    asm volatile("cp.async.cg.shared.global [%0], [%1], 16;"
                 :: "r"(dst), "l"(src));
}

// ============================================================================
// Kernel 1: WhT[b][h][o][n] fp16 + alpha_src/alpha_dst (fp32)
// ============================================================================
__global__ __launch_bounds__(256, 4) void wh_kernel(
    const float* __restrict__ x, const float* __restrict__ W,
    const float* __restrict__ a_src, const float* __restrict__ a_dst)
{
    __shared__ __align__(16) float x_sm[32][IN_D];      // 16 KB
    __shared__ __align__(16) float w_sm[IN_D * Oo];     // 16 KB (reused: 32x33 transpose)

    const int b   = blockIdx.z;
    const int h   = blockIdx.y;
    const int n0  = blockIdx.x * 32;
    const int tid = threadIdx.x;
    const int lane = tid & 31;       // = o
    const int wq   = tid >> 5;       // warp -> 4 rows

    {   // x tile
        const float4* xg = (const float4*)(x + ((size_t)b*Nn + n0)*IN_D);
        float4* xs = (float4*)&x_sm[0][0];
        #pragma unroll
        for (int k = 0; k < 4; ++k) xs[tid + k*256] = xg[tid + k*256];
    }
    {   // W[h]
        const float4* wg = (const float4*)(W + (size_t)h*IN_D*Oo);
        float4* ws = (float4*)w_sm;
        #pragma unroll
        for (int k = 0; k < 4; ++k) ws[tid + k*256] = wg[tid + k*256];
    }
    __syncthreads();

    float acc[4] = {0.f, 0.f, 0.f, 0.f};
    #pragma unroll 8
    for (int f4 = 0; f4 < IN_D/4; ++f4) {
        float4 xv[4];
        #pragma unroll
        for (int r = 0; r < 4; ++r)
            xv[r] = ((const float4*)&x_sm[wq*4 + r][0])[f4];
        #pragma unroll
        for (int u = 0; u < 4; ++u) {
            float wv = w_sm[(f4*4 + u)*Oo + lane];
            acc[0] += (u==0?xv[0].x:u==1?xv[0].y:u==2?xv[0].z:xv[0].w) * wv;
            acc[1] += (u==0?xv[1].x:u==1?xv[1].y:u==2?xv[1].z:xv[1].w) * wv;
            acc[2] += (u==0?xv[2].x:u==1?xv[2].y:u==2?xv[2].z:xv[2].w) * wv;
            acc[3] += (u==0?xv[3].x:u==1?xv[3].y:u==2?xv[3].z:xv[3].w) * wv;
        }
    }

    const float asv = a_src[h*Oo + lane];
    const float adv = a_dst[h*Oo + lane];
    #pragma unroll
    for (int r = 0; r < 4; ++r) {
        int n = n0 + wq*4 + r;
        float ps = acc[r] * asv;
        float pd = acc[r] * adv;
        #pragma unroll
        for (int s = 16; s > 0; s >>= 1) {
            ps += __shfl_xor_sync(~0u, ps, s);
            pd += __shfl_xor_sync(~0u, pd, s);
        }
        if (lane == 0) {
            g_asrc[((size_t)b*Hh + h)*Nn + n] = ps;
            g_adst[((size_t)b*Hh + h)*Nn + n] = pd;
        }
    }

    // transpose via w_sm overlay (everyone done reading w_sm)
    __syncthreads();
    #pragma unroll
    for (int r = 0; r < 4; ++r)
        w_sm[(wq*4 + r)*33 + lane] = acc[r];
    __syncthreads();

    // WhT half store: [o][n], thread writes 4 n-halves (8B), coalesced
    {
        int o  = tid >> 3;
        int ng = tid & 7;
        float v0 = w_sm[(ng*4 + 0)*33 + o];
        float v1 = w_sm[(ng*4 + 1)*33 + o];
        float v2 = w_sm[(ng*4 + 2)*33 + o];
        float v3 = w_sm[(ng*4 + 3)*33 + o];
        uint2 pk;
        pk.x = f2h2(v1, v0);
        pk.y = f2h2(v3, v2);
        *(uint2*)(g_WhT + (((size_t)b*Hh + h)*Oo + o)*Nn + n0 + ng*4) = pk;
    }
}

// ============================================================================
// Kernel 2: per-(b,h) max of alpha_dst
// ============================================================================
__global__ __launch_bounds__(256) void maxd_kernel()
{
    const int bh  = blockIdx.x;
    const int tid = threadIdx.x;
    float m = -1e30f;
    for (int n = tid; n < Nn; n += 256)
        m = fmaxf(m, g_adst[(size_t)bh*Nn + n]);
    __shared__ float red[256];
    red[tid] = m;
    __syncthreads();
    for (int s = 128; s > 0; s >>= 1) {
        if (tid < s) red[tid] = fmaxf(red[tid], red[tid + s]);
        __syncthreads();
    }
    if (tid == 0) g_maxd[bh] = red[0];
}

// ============================================================================
// Kernel 3: fused masked-softmax + AV via mma.sync.m16n8k16.f16 (fp32 accum)
// grid (32, 2, 4) = 256 CTAs; 256 threads; 4 heads/CTA; 2 CTAs/SM.
// R14 skeleton + fragment loads via ldmatrix:
//  A: 2x m8n8.x4 (non-trans) — tiles rows0-7/k0-7, rows8-15/k0-7,
//     rows0-7/k8-15, rows8-15/k8-15 -> a0..a3
//  B: 2x m8n8.x4 NON-TRANS (wh_sm is n-major; the .col B fragment wants
//     k-consecutive halves per lane, which n-major rows already provide;
//     R15's .trans was the bug)
// SMEM (dynamic, 74752 B):
//   p_sm  half [4][4][64][24]   bytes 0..49151      (sub-buffer stride 12288)
//   wh_sm half [4][4][32][24]   bytes 49152..73727  (sub-buffer stride 6144)
//   ej_sm      [4][4][4][16B]   bytes 73728..74751
// ============================================================================
__global__ __launch_bounds__(256, 2) void gat_mma(const float* __restrict__ adj,
                                                  float* __restrict__ out)
{
    extern __shared__ char smraw[];
    __half* p_sm  = (__half*)smraw;                  // halves, row stride 48 B
    __half* wh_sm = (__half*)(smraw + 49152);        // halves, row stride 48 B
    char*   ej_sm = smraw + 73728;

    const int tid  = threadIdx.x;
    const int lane = tid & 31;
    const int wid  = tid >> 5;       // 0..7
    const int hL   = wid >> 1;       // local mma head 0..3
    const int mh   = wid & 1;        // row half
    const int b    = blockIdx.z;
    const int h0   = blockIdx.y * HG;
    const int i0   = blockIdx.x * BI;
    const int ith  = tid >> 2;       // p-gen row 0..63
    const int j4   = tid & 3;        // p-gen j-quad within sub-chunk
    const int iglob = i0 + ith;
    const int g  = lane >> 2;
    // ldmatrix lane decomposition
    const int lr = lane & 7;         // row within 8x8 tile
    const int lt = lane >> 3;        // tile index 0..3
    // ej staging (tid<64): thread -> (sub, head, j-pair)
    const int zs = tid >> 5;         // sub-chunk 0..1
    const int zh = (tid >> 3) & 3;   // head 0..3
    const int zp = tid & 7;          // j-pair 0..7
    // wh cp.async mapping: per sub-chunk, tid covers 4h x 32o x 2sk
    const int sh = tid >> 6;         // head 0..3
    const int so = (tid >> 1) & 31;  // o-row
    const int sk = tid & 1;          // 16B half-row

    const uint32_t p_u32  = (uint32_t)__cvta_generic_to_shared(p_sm);
    const uint32_t wh_u32 = (uint32_t)__cvta_generic_to_shared(wh_sm);

    // per-(h,i) hoisted exponentials as half2 broadcasts
    __half2 E1i2[HG], E2i2[HG];
    #pragma unroll
    for (int h = 0; h < HG; ++h) {
        float s  = g_asrc[((size_t)(b*Hh + h0 + h))*Nn + iglob];
        float md = g_maxd[b*Hh + h0 + h];
        float t  = s + md;
        float m  = fmaxf(t, 0.2f*t);                 // lrelu monotone -> row max
        E1i2[h] = __float2half2_rn(ex2f_fast((s - m)*LOG2E));
        E2i2[h] = __float2half2_rn(ex2f_fast((0.2f*s - m)*LOG2E));
    }

    // self-loop patch: fires at iteration itd, sub-chunk sd, only if this
    // thread's j-quad contains the diagonal column of its row
    const int itd = iglob >> 5;
    const int sd  = (iglob >> 4) & 1;
    const bool dhit = (((iglob >> 2) & 3) == j4);
    const int du = iglob & 3;
    const uint32_t fix01 = dhit ? (du==0 ? 0x3C00u : du==1 ? 0x3C000000u : 0u) : 0u;
    const uint32_t fix23 = dhit ? (du==2 ? 0x3C00u : du==3 ? 0x3C000000u : 0u) : 0u;

    const float4*  arow  = (const float4*)(adj + ((size_t)b*Nn + iglob)*Nn);
    const __half*  whtg  = g_WhT + (((size_t)b*Hh + h0)*Oo)*Nn;
    const float*   adstb = g_adst + ((size_t)b*Hh + h0)*Nn;

    // ---- prologue: cp.async wh iteration 0 (both sub-chunks) -> bufs 0,1 ----
    #pragma unroll
    for (int s = 0; s < 2; ++s)
        cp_async16(wh_u32 + (uint32_t)(s*6144 + sh*1536 + so*48 + sk*16),
                   whtg + ((size_t)sh*Oo + so)*Nn + s*KC + sk*8);
    asm volatile("cp.async.commit_group;" ::: "memory");

    // ej iteration 0 -> bufs 0,1; prefetch iteration-1 dl pair
    float2 dlv = make_float2(0.f, 0.f);
    if (tid < 64) {
        float2 d0 = *(const float2*)(adstb + (size_t)zh*Nn + zs*KC + zp*2);
        float a0 = d0.x*LOG2E, a1 = d0.y*LOG2E;
        uint32_t e1 = f2h2(ex2f_fast(a1), ex2f_fast(a0));
        uint32_t e2 = f2h2(ex2f_fast(0.2f*a1), ex2f_fast(0.2f*a0));
        int base = zs*256 + zh*64 + (zp>>1)*16 + (zp&1)*4;
        *(uint32_t*)(ej_sm + base)     = e1;
        *(uint32_t*)(ej_sm + base + 8) = e2;
        dlv = *(const float2*)(adstb + (size_t)zh*Nn + 32 + zs*KC + zp*2);
    }
    float4 adjv0 = arow[j4];          // iteration-0 adj, sub 0
    float4 adjv1 = arow[4 + j4];      // iteration-0 adj, sub 1

    float acc[2][4][4];
    float accz[2][4];
    #pragma unroll
    for (int m = 0; m < 2; ++m) {
        #pragma unroll
        for (int nt = 0; nt < 4; ++nt)
            #pragma unroll
            for (int r = 0; r < 4; ++r) acc[m][nt][r] = 0.f;
        #pragma unroll
        for (int r = 0; r < 4; ++r) accz[m][r] = 0.f;
    }
    // ones-column B fragment (constant): lanes with g==0 hold column n=0
    const uint32_t bones = (g == 0) ? 0x3C003C00u : 0u;

    // ldmatrix per-lane base offsets (within a sub-buffer)
    // A tiles: t0: rows 0-7/k0-7, t1: rows 8-15/k0-7, t2: rows 0-7/k8-15,
    //          t3: rows 8-15/k8-15  -> addr = ((lt&1)*8 + lr)*48 + (lt>>1)*16
    const uint32_t a_off = (uint32_t)(((lt & 1)*8 + lr)*48 + (lt >> 1)*16);
    // B tiles (non-trans): t0:(n0-7,k0-7) t1:(n0-7,k8-15) t2:(n8-15,k0-7)
    //          t3:(n8-15,k8-15) -> addr = ((lt>>1)*8 + lr)*48 + (lt&1)*16
    const uint32_t b_off = (uint32_t)(((lt >> 1)*8 + lr)*48 + (lt & 1)*16);

    __syncthreads();                 // ej[0,1] visible

    for (int it = 0; it < ITN; ++it) {
        const int pb = (it & 1) * 2; // sub-buffer pair base (0 or 2)

        // ======== phase A ========
        // stage ej(it+1) -> bufs pb^2, pb^2+1
        if (it + 1 < ITN && tid < 64) {
            float a0 = dlv.x*LOG2E, a1 = dlv.y*LOG2E;
            uint32_t e1 = f2h2(ex2f_fast(a1), ex2f_fast(a0));
            uint32_t e2 = f2h2(ex2f_fast(0.2f*a1), ex2f_fast(0.2f*a0));
            int base = ((pb^2) + zs)*256 + zh*64 + (zp>>1)*16 + (zp&1)*4;
            *(uint32_t*)(ej_sm + base)     = e1;
            *(uint32_t*)(ej_sm + base + 8) = e2;
        }

        // p-gen for both sub-chunks x 4 heads
        #pragma unroll
        for (int s = 0; s < 2; ++s) {
            const float4 av = s ? adjv1 : adjv0;
            uint32_t m01u = f2h2(av.y, av.x);
            uint32_t m23u = f2h2(av.w, av.z);
            if (it == itd && s == sd) { m01u |= fix01; m23u |= fix23; }
            const __half2 msk01 = u2h2(m01u);
            const __half2 msk23 = u2h2(m23u);
            const int sb = pb + s;
            #pragma unroll
            for (int h = 0; h < HG; ++h) {
                uint4 e = *(const uint4*)(ej_sm + sb*256 + h*64 + j4*16);
                __half2 w01 = __hmax2(__hmul2(E1i2[h], u2h2(e.x)),
                                      __hmul2(E2i2[h], u2h2(e.z)));
                __half2 w23 = __hmax2(__hmul2(E1i2[h], u2h2(e.y)),
                                      __hmul2(E2i2[h], u2h2(e.w)));
                w01 = __hmul2(w01, msk01);
                w23 = __hmul2(w23, msk23);
                uint2 pk; pk.x = h2u2(w01); pk.y = h2u2(w23);
                *(uint2*)((char*)p_sm + sb*12288 + h*3072 + ith*48 + j4*8) = pk;
            }
        }

        __syncthreads();             // the ONE barrier per iteration

        // ======== phase B ========
        if (it + 1 < ITN) {
            #pragma unroll
            for (int s = 0; s < 2; ++s)
                cp_async16(wh_u32 + (uint32_t)(((pb^2)+s)*6144 + sh*1536 + so*48 + sk*16),
                           whtg + ((size_t)sh*Oo + so)*Nn + (it+1)*32 + s*KC + sk*8);
            asm volatile("cp.async.commit_group;" ::: "memory");
            asm volatile("cp.async.wait_group 1;" ::: "memory");
        } else {
            asm volatile("cp.async.wait_group 0;" ::: "memory");
        }

        // mma over both sub-chunks: warp (hL, mh), fragments via ldmatrix
        #pragma unroll
        for (int s = 0; s < 2; ++s) {
            const int sb = pb + s;
            const uint32_t ph_u = p_u32 + (uint32_t)(sb*12288 + hL*3072 + mh*32*48);
            const uint32_t wt_u = wh_u32 + (uint32_t)(sb*6144 + hL*1536);

            uint32_t bf[4][2];
            asm volatile(
                "ldmatrix.sync.aligned.m8n8.x4.shared.b16 {%0,%1,%2,%3}, [%4];"
                : "=r"(bf[0][0]), "=r"(bf[0][1]), "=r"(bf[1][0]), "=r"(bf[1][1])
                : "r"(wt_u + b_off));
            asm volatile(
                "ldmatrix.sync.aligned.m8n8.x4.shared.b16 {%0,%1,%2,%3}, [%4];"
                : "=r"(bf[2][0]), "=r"(bf[2][1]), "=r"(bf[3][0]), "=r"(bf[3][1])
                : "r"(wt_u + b_off + 16u*48u));

            #pragma unroll
            for (int m = 0; m < 2; ++m) {
                uint32_t a0, a1, a2, a3;
                asm volatile(
                    "ldmatrix.sync.aligned.m8n8.x4.shared.b16 {%0,%1,%2,%3}, [%4];"
                    : "=r"(a0), "=r"(a1), "=r"(a2), "=r"(a3)
                    : "r"(ph_u + (uint32_t)(m*16*48) + a_off));
                #pragma unroll
                for (int nt = 0; nt < 4; ++nt) {
                    asm volatile(
                      "mma.sync.aligned.m16n8k16.row.col.f32.f16.f16.f32 "
                      "{%0,%1,%2,%3}, {%4,%5,%6,%7}, {%8,%9}, {%0,%1,%2,%3};"
                      : "+f"(acc[m][nt][0]), "+f"(acc[m][nt][1]),
                        "+f"(acc[m][nt][2]), "+f"(acc[m][nt][3])
                      : "r"(a0), "r"(a1), "r"(a2), "r"(a3),
                        "r"(bf[nt][0]), "r"(bf[nt][1]));
                }
                // Z accumulation: ones-column B (register constant)
                asm volatile(
                  "mma.sync.aligned.m16n8k16.row.col.f32.f16.f16.f32 "
                  "{%0,%1,%2,%3}, {%4,%5,%6,%7}, {%8,%9}, {%0,%1,%2,%3};"
                  : "+f"(accz[m][0]), "+f"(accz[m][1]),
                    "+f"(accz[m][2]), "+f"(accz[m][3])
                  : "r"(a0), "r"(a1), "r"(a2), "r"(a3),
                    "r"(bones), "r"(bones));
            }
        }

        // prefetches for it+1 / it+2
        if (it + 1 < ITN) {
            adjv0 = arow[(it+1)*8 + j4];
            adjv1 = arow[(it+1)*8 + 4 + j4];
        }
        if (it + 2 < ITN && tid < 64)
            dlv = *(const float2*)(adstb + (size_t)zh*Nn + (it+2)*32 + zs*KC + zp*2);
    }

    // ---- epilogue: Z broadcast (t4==0 lanes hold column 0), normalize ----
    {
        const int t4 = lane & 3;
        float* ob = out + ((size_t)b*Nn + i0 + mh*32)*(Hh*Oo) + (h0 + hL)*Oo;
        #pragma unroll
        for (int m = 0; m < 2; ++m) {
            int r0 = m*16 + g;
            float z0 = __shfl_sync(~0u, accz[m][0], lane & ~3);
            float z1 = __shfl_sync(~0u, accz[m][2], lane & ~3);
            float zi0 = 1.f / z0;
            float zi1 = 1.f / z1;
            #pragma unroll
            for (int nt = 0; nt < 4; ++nt) {
                int o = nt*8 + 2*t4;
                float2 v0, v1;
                v0.x = fmaxf(acc[m][nt][0]*zi0, 0.f);
                v0.y = fmaxf(acc[m][nt][1]*zi0, 0.f);
                v1.x = fmaxf(acc[m][nt][2]*zi1, 0.f);
                v1.y = fmaxf(acc[m][nt][3]*zi1, 0.f);
                *(float2*)(ob + (size_t)r0*(Hh*Oo) + o)       = v0;
                *(float2*)(ob + (size_t)(r0 + 8)*(Hh*Oo) + o) = v1;
            }
        }
    }
}

// ============================================================================
extern "C" void kernel_launch(void* const* d_in, const int* in_sizes, int n_in,
                              void* d_out, int out_size)
{
    (void)in_sizes; (void)n_in; (void)out_size;
    const float* x     = (const float*)d_in[0];
    const float* adj   = (const float*)d_in[1];
    const float* W     = (const float*)d_in[2];
    const float* a_src = (const float*)d_in[3];
    const float* a_dst = (const float*)d_in[4];
    float* out = (float*)d_out;

    wh_kernel<<<dim3(Nn/32, Hh, Bb), 256>>>(x, W, a_src, a_dst);
    maxd_kernel<<<Bb*Hh, 256>>>();

    static const int smem_bytes = 74752;
    cudaFuncSetAttribute(gat_mma, cudaFuncAttributeMaxDynamicSharedMemorySize,
                         smem_bytes);
    gat_mma<<<dim3(Nn/BI, Hh/HG, Bb), 256, smem_bytes>>>(adj, out);
}